// round 13
// baseline (speedup 1.0000x reference)
#include <cuda_runtime.h>
#include <math.h>

// Problem constants (fixed by the reference setup_inputs)
#define Bb 2
#define Tt 12
#define Nn 4096
#define Kk 16
#define Hh 4
#define Cc 16
#define Vv 3

#define BTNH (Bb*Tt*Nn*Hh)                  // 393216
#define NEDGE ((size_t)Bb*Tt*Nn*Kk)         // 1572864
#define U_SIZE ((size_t)Bb*Tt*Nn*Kk*Hh)     // 6291456
#define BRNH (Bb*(Tt-1)*Nn*Hh)              // 360448

#define SZ_FEATURES 6291456
#define SZ_MULTIQ   3072
#define SZ_MULTIM   1024
#define SZ_NEAREST  69632

#define FLT_MIN_NORMAL 1.17549435e-38f

__device__ __forceinline__ float ftz(float x) {
    return (fabsf(x) < FLT_MIN_NORMAL) ? 0.f : x;
}

// Scratch (static device memory — no runtime allocation)
__device__ float g_buf[(size_t)BTNH * Cc];   // general fallback only
__device__ float deg_buf[BTNH];              // [bt][n][h]

// ---------------------------------------------------------------------------
// K1 (fallback only): g = multiM @ f. Each block self-checks M diagonality
// and early-outs (diagonal case never touches g_buf).
// ---------------------------------------------------------------------------
__global__ void k1_compute_g(const float* __restrict__ f,
                             const float* __restrict__ M)
{
    __shared__ float sM[Hh * Cc * Cc];
    __shared__ int s_ok;
    if (threadIdx.x == 0) s_ok = 1;
    for (int i = threadIdx.x; i < Hh * Cc * Cc; i += blockDim.x) sM[i] = M[i];
    __syncthreads();
    for (int i = threadIdx.x; i < Hh * Cc * Cc; i += blockDim.x) {
        int r = (i / Cc) % Cc, c = i % Cc;
        if (r != c && sM[i] != 0.f) s_ok = 0;   // benign race: only writes 0
    }
    __syncthreads();
    if (s_ok) return;                            // diagonal: fast path skips g

    int idx = blockIdx.x * blockDim.x + threadIdx.x;
    if (idx >= BTNH) return;
    int h = idx & (Hh - 1);

    const float* fv = f + (size_t)idx * Cc;
    float x[Cc];
#pragma unroll
    for (int c = 0; c < Cc; c += 4) {
        float4 t = *reinterpret_cast<const float4*>(fv + c);
        x[c] = t.x; x[c+1] = t.y; x[c+2] = t.z; x[c+3] = t.w;
    }
    const float* Mh = sM + h * Cc * Cc;
    float y[Cc];
#pragma unroll
    for (int i = 0; i < Cc; i++) {
        float s = 0.f;
#pragma unroll
        for (int j = 0; j < Cc; j++) s = __fadd_rn(s, __fmul_rn(Mh[i * Cc + j], x[j]));
        y[i] = s;
    }
    float* gv = g_buf + (size_t)idx * Cc;
#pragma unroll
    for (int c = 0; c < Cc; c += 4) {
        float4 t; t.x = y[c]; t.y = y[c+1]; t.z = y[c+2]; t.w = y[c+3];
        *reinterpret_cast<float4*>(gv + c) = t;
    }
}

// ---------------------------------------------------------------------------
// K2: one thread per (bt,n,h); 16-neighbor loop (R8/R12 winning layout).
// Per-block self-analysis of M: diag -> src=f, mv=Mdiag; else src=g_buf, mv=1.
// ---------------------------------------------------------------------------
__global__ void k2_w_deg(const float* __restrict__ f,
                         const float* __restrict__ M,
                         const int* __restrict__ nn,
                         float* __restrict__ out_u)
{
    __shared__ float sM[Hh * Cc * Cc];
    __shared__ float sm[Hh * Cc];
    __shared__ int s_ok;
    if (threadIdx.x == 0) s_ok = 1;
    for (int i = threadIdx.x; i < Hh * Cc * Cc; i += blockDim.x) sM[i] = M[i];
    __syncthreads();
    for (int i = threadIdx.x; i < Hh * Cc * Cc; i += blockDim.x) {
        int r = (i / Cc) % Cc, c = i % Cc;
        if (r != c && sM[i] != 0.f) s_ok = 0;
    }
    __syncthreads();
    int diag = s_ok;
    for (int i = threadIdx.x; i < Hh * Cc; i += blockDim.x)
        sm[i] = diag ? sM[i * Cc + (i % Cc)] : 1.0f;   // sM[(h*Cc+c)*Cc + c]
    __syncthreads();

    int idx = blockIdx.x * blockDim.x + threadIdx.x;
    if (idx >= BTNH) return;
    int h  = idx & (Hh - 1);
    int n  = (idx >> 2) & (Nn - 1);
    int bt = idx >> 14;

    const float* src = diag ? f : g_buf;
    const int*   nrow  = nn + n * (Kk + 1) + 1;
    float* ubase = out_u + (((size_t)bt * Nn + n) * Kk) * Hh + h;

    const float* fvi = src + (size_t)idx * Cc;
    float fi[Cc], mv[Cc];
#pragma unroll
    for (int c = 0; c < Cc; c += 4) {
        float4 t = *reinterpret_cast<const float4*>(fvi + c);
        fi[c] = t.x; fi[c+1] = t.y; fi[c+2] = t.z; fi[c+3] = t.w;
    }
#pragma unroll
    for (int c = 0; c < Cc; c++) mv[c] = sm[h * Cc + c];

    const float* fbase = src + (size_t)bt * Nn * Hh * Cc;
    float deg = 0.f;
#pragma unroll 4
    for (int k = 0; k < Kk; k++) {
        int j = nrow[k];
        float w = 0.f;
        if (j >= 0) {
            const float* fj = fbase + ((size_t)j * Hh + h) * Cc;
            float s = 0.f;
#pragma unroll
            for (int c = 0; c < Cc; c += 4) {
                float4 t = *reinterpret_cast<const float4*>(fj + c);
                float a0 = __fmul_rn(mv[c],   __fsub_rn(fi[c],   t.x));
                float a1 = __fmul_rn(mv[c+1], __fsub_rn(fi[c+1], t.y));
                float a2 = __fmul_rn(mv[c+2], __fsub_rn(fi[c+2], t.z));
                float a3 = __fmul_rn(mv[c+3], __fsub_rn(fi[c+3], t.w));
                s = __fadd_rn(s, __fmul_rn(a0, a0));
                s = __fadd_rn(s, __fmul_rn(a1, a1));
                s = __fadd_rn(s, __fmul_rn(a2, a2));
                s = __fadd_rn(s, __fmul_rn(a3, a3));
            }
            w = ftz(expf(-s));
        }
        deg = __fadd_rn(deg, w);
        ubase[(size_t)k * Hh] = w;
    }
    deg_buf[idx] = deg;
}

// ---------------------------------------------------------------------------
// K3: one thread per edge (bt,n,k), float4 over h (R9/R12 winning layout).
// ---------------------------------------------------------------------------
__global__ void __launch_bounds__(256) k3_normalize(
        const int* __restrict__ nn,
        float* __restrict__ out_u)
{
    size_t idx = (size_t)blockIdx.x * blockDim.x + threadIdx.x;
    if (idx >= NEDGE) return;
    int k  = (int)(idx & 15);
    int n  = (int)((idx >> 4) & (Nn - 1));
    int bt = (int)(idx >> 16);

    const float4* degv = reinterpret_cast<const float4*>(deg_buf);
    float4 di = degv[(size_t)bt * Nn + n];

    int j  = nn[n * (Kk + 1) + 1 + k];
    int jj = j % Nn; if (jj < 0) jj += Nn;
    float4 dj = degv[(size_t)bt * Nn + jj];

    float4* uv = reinterpret_cast<float4*>(out_u) + ((size_t)bt * Nn + n) * Kk + k;
    float4 u = *uv;

    float P, dm;
    P = ftz(__fmul_rn(di.x, dj.x)); dm = sqrtf(P);
    u.x = ftz(__fmul_rn(u.x, (dm > 0.f) ? __fdiv_rn(1.f, dm) : 0.f));
    P = ftz(__fmul_rn(di.y, dj.y)); dm = sqrtf(P);
    u.y = ftz(__fmul_rn(u.y, (dm > 0.f) ? __fdiv_rn(1.f, dm) : 0.f));
    P = ftz(__fmul_rn(di.z, dj.z)); dm = sqrtf(P);
    u.z = ftz(__fmul_rn(u.z, (dm > 0.f) ? __fdiv_rn(1.f, dm) : 0.f));
    P = ftz(__fmul_rn(di.w, dj.w)); dm = sqrtf(P);
    u.w = ftz(__fmul_rn(u.w, (dm > 0.f) ? __fdiv_rn(1.f, dm) : 0.f));

    *uv = u;
}

// ---------------------------------------------------------------------------
// K4: temporal path. Per-block self-analysis of Q (diag => bit-exact fast path).
// ---------------------------------------------------------------------------
__global__ void k4_temporal(const float* __restrict__ f,
                            const float* __restrict__ Q,
                            float* __restrict__ out_d)
{
    __shared__ float sQ[Vv * Hh * Cc * Cc];   // 12 KB
    __shared__ float sQd[Vv * Hh * Cc];
    __shared__ int s_ok;
    if (threadIdx.x == 0) s_ok = 1;
    for (int i = threadIdx.x; i < Vv * Hh * Cc * Cc; i += blockDim.x) sQ[i] = Q[i];
    __syncthreads();
    for (int i = threadIdx.x; i < Vv * Hh * Cc * Cc; i += blockDim.x) {
        int r = (i / Cc) % Cc, c = i % Cc;
        if (r != c && sQ[i] != 0.f) s_ok = 0;
    }
    __syncthreads();
    int diag = s_ok;
    if (diag) {
        for (int i = threadIdx.x; i < Vv * Hh * Cc; i += blockDim.x)
            sQd[i] = sQ[i * Cc + (i % Cc)];
    }
    __syncthreads();

    int idx = blockIdx.x * blockDim.x + threadIdx.x;
    if (idx >= BRNH) return;
    int h  = idx & (Hh - 1);
    int n  = (idx >> 2) & (Nn - 1);
    int br = idx >> 14;
    int r  = br % (Tt - 1);
    int b  = br / (Tt - 1);
    int tcur = r + 1;

    const float* fb = f + (size_t)b * Tt * Nn * Hh * Cc;
    const float* fc = fb + (((size_t)tcur * Nn + n) * Hh + h) * Cc;

    float xc[Cc];
#pragma unroll
    for (int c = 0; c < Cc; c += 4) {
        float4 t = *reinterpret_cast<const float4*>(fc + c);
        xc[c] = t.x; xc[c+1] = t.y; xc[c+2] = t.z; xc[c+3] = t.w;
    }

    float wd[Vv];
    float indeg = 0.f;
#pragma unroll
    for (int v = 0; v < Vv; v++) {
        float w = 0.f;
        if (v <= r) {
            int tp = r - v;
            const float* fp = fb + (((size_t)tp * Nn + n) * Hh + h) * Cc;
            float d[Cc];
#pragma unroll
            for (int c = 0; c < Cc; c += 4) {
                float4 t = *reinterpret_cast<const float4*>(fp + c);
                d[c]   = __fsub_rn(t.x, xc[c]);
                d[c+1] = __fsub_rn(t.y, xc[c+1]);
                d[c+2] = __fsub_rn(t.z, xc[c+2]);
                d[c+3] = __fsub_rn(t.w, xc[c+3]);
            }
            if (diag) {
                const float* qv = sQd + (v * Hh + h) * Cc;
#pragma unroll
                for (int i = 0; i < Cc; i++) {
                    float a = __fmul_rn(qv[i], d[i]);
                    float e = expf(-__fmul_rn(a, a));
                    w = __fadd_rn(w, e);
                }
            } else {
                const float* Qh = sQ + (v * Hh + h) * Cc * Cc;
#pragma unroll
                for (int i = 0; i < Cc; i++) {
                    float a = 0.f;
#pragma unroll
                    for (int jx = 0; jx < Cc; jx++)
                        a = __fadd_rn(a, __fmul_rn(Qh[i * Cc + jx], d[jx]));
                    float e = expf(-__fmul_rn(a, a));
                    w = __fadd_rn(w, e);
                }
            }
        }
        wd[v] = w;
        indeg = __fadd_rn(indeg, w);
    }
    float inv = (indeg > 0.f) ? __fdiv_rn(1.f, indeg) : 0.f;

    size_t obase = ((size_t)(b * (Tt - 1) + r)) * Vv * Nn * Hh + (size_t)n * Hh + h;
#pragma unroll
    for (int v = 0; v < Vv; v++)
        out_d[obase + (size_t)v * Nn * Hh] = __fmul_rn(wd[v], inv);
}

// ---------------------------------------------------------------------------
// Side-stream handles: created lazily on the FIRST call (the uncaptured
// correctness run), reused identically on every subsequent call so the
// captured work is the same every time. No device memory is allocated.
// ---------------------------------------------------------------------------
static cudaStream_t g_side = nullptr;
static cudaEvent_t  g_fork = nullptr;
static cudaEvent_t  g_join = nullptr;

extern "C" void kernel_launch(void* const* d_in, const int* in_sizes, int n_in,
                              void* d_out, int out_size)
{
    const float* features = nullptr;
    const float* multiQ   = nullptr;
    const float* multiM   = nullptr;
    const int*   nearest  = nullptr;
    for (int i = 0; i < n_in; i++) {
        switch (in_sizes[i]) {
            case SZ_FEATURES: features = (const float*)d_in[i]; break;
            case SZ_MULTIQ:   multiQ   = (const float*)d_in[i]; break;
            case SZ_MULTIM:   multiM   = (const float*)d_in[i]; break;
            case SZ_NEAREST:  nearest  = (const int*)  d_in[i]; break;
            default: break;
        }
    }

    float* out_u = (float*)d_out;
    float* out_d = (float*)d_out + U_SIZE;

    if (g_side == nullptr) {
        if (cudaStreamCreateWithFlags(&g_side, cudaStreamNonBlocking) != cudaSuccess)
            g_side = nullptr;
        if (g_side) {
            cudaEventCreateWithFlags(&g_fork, cudaEventDisableTiming);
            cudaEventCreateWithFlags(&g_join, cudaEventDisableTiming);
        }
    }

    const int thr = 256;
    bool forked = (g_side != nullptr && g_fork != nullptr && g_join != nullptr);

    if (forked) {
        // fork: k4 is independent of k1/k2/k3 — run it concurrently
        cudaEventRecord(g_fork, 0);
        cudaStreamWaitEvent(g_side, g_fork, 0);
        k4_temporal<<<(BRNH + thr - 1) / thr, thr, 0, g_side>>>(features, multiQ, out_d);
        cudaEventRecord(g_join, g_side);
    }

    k1_compute_g<<<(BTNH + thr - 1) / thr, thr>>>(features, multiM);  // no-op when M diag
    k2_w_deg<<<(BTNH + thr - 1) / thr, thr>>>(features, multiM, nearest, out_u);
    k3_normalize<<<(int)((NEDGE + thr - 1) / thr), thr>>>(nearest, out_u);

    if (forked) {
        cudaStreamWaitEvent(0, g_join, 0);
    } else {
        k4_temporal<<<(BRNH + thr - 1) / thr, thr>>>(features, multiQ, out_d);
    }
}

// round 17
// speedup vs baseline: 1.0619x; 1.0619x over previous
#include <cuda_runtime.h>
#include <math.h>

// Problem constants (fixed by the reference setup_inputs)
#define Bb 2
#define Tt 12
#define Nn 4096
#define Kk 16
#define Hh 4
#define Cc 16
#define Vv 3

#define BTNH (Bb*Tt*Nn*Hh)                  // 393216
#define NEDGE ((size_t)Bb*Tt*Nn*Kk)         // 1572864
#define U_SIZE ((size_t)Bb*Tt*Nn*Kk*Hh)     // 6291456
#define BRNH (Bb*(Tt-1)*Nn*Hh)              // 360448

#define SZ_FEATURES 6291456
#define SZ_MULTIQ   3072
#define SZ_MULTIM   1024
#define SZ_NEAREST  69632

#define FLT_MIN_NORMAL 1.17549435e-38f

__device__ __forceinline__ float ftz(float x) {
    return (fabsf(x) < FLT_MIN_NORMAL) ? 0.f : x;
}

// Scratch / analysis results (static device memory — no runtime allocation)
__device__ float g_buf[(size_t)BTNH * Cc];   // general fallback only
__device__ float deg_buf[BTNH];              // [bt][n][h]
__device__ int   d_diag_flags[2];
__device__ float d_Mdiag[Hh * Cc];
__device__ float d_Qdiag[Vv * Hh * Cc];

// ---------------------------------------------------------------------------
// K0: analyze multiM / multiQ once (diagonal => bit-exact fast path allowed)
// ---------------------------------------------------------------------------
__global__ void k0_analyze(const float* __restrict__ M,
                           const float* __restrict__ Q)
{
    __shared__ int okM, okQ;
    if (threadIdx.x == 0) { okM = 1; okQ = 1; }
    __syncthreads();

    for (int i = threadIdx.x; i < Hh * Cc * Cc; i += blockDim.x) {
        int r = (i / Cc) % Cc, c = i % Cc;
        float v = M[i];
        if (r != c && v != 0.f) atomicAnd(&okM, 0);
        if (r == c) d_Mdiag[(i / (Cc * Cc)) * Cc + r] = v;
    }
    for (int i = threadIdx.x; i < Vv * Hh * Cc * Cc; i += blockDim.x) {
        int r = (i / Cc) % Cc, c = i % Cc;
        float v = Q[i];
        if (r != c && v != 0.f) atomicAnd(&okQ, 0);
        if (r == c) d_Qdiag[(i / (Cc * Cc)) * Cc + r] = v;
    }
    __syncthreads();
    if (threadIdx.x == 0) { d_diag_flags[0] = okM; d_diag_flags[1] = okQ; }
}

// ---------------------------------------------------------------------------
// K1 (fallback only): g = multiM @ f. Early-out when multiM diagonal.
// ---------------------------------------------------------------------------
__global__ void k1_compute_g(const float* __restrict__ f,
                             const float* __restrict__ M)
{
    if (d_diag_flags[0]) return;

    __shared__ float sM[Hh * Cc * Cc];
    for (int i = threadIdx.x; i < Hh * Cc * Cc; i += blockDim.x) sM[i] = M[i];
    __syncthreads();

    int idx = blockIdx.x * blockDim.x + threadIdx.x;
    if (idx >= BTNH) return;
    int h = idx & (Hh - 1);

    const float* fv = f + (size_t)idx * Cc;
    float x[Cc];
#pragma unroll
    for (int c = 0; c < Cc; c += 4) {
        float4 t = *reinterpret_cast<const float4*>(fv + c);
        x[c] = t.x; x[c+1] = t.y; x[c+2] = t.z; x[c+3] = t.w;
    }
    const float* Mh = sM + h * Cc * Cc;
    float y[Cc];
#pragma unroll
    for (int i = 0; i < Cc; i++) {
        float s = 0.f;
#pragma unroll
        for (int j = 0; j < Cc; j++) s = __fadd_rn(s, __fmul_rn(Mh[i * Cc + j], x[j]));
        y[i] = s;
    }
    float* gv = g_buf + (size_t)idx * Cc;
#pragma unroll
    for (int c = 0; c < Cc; c += 4) {
        float4 t; t.x = y[c]; t.y = y[c+1]; t.z = y[c+2]; t.w = y[c+3];
        *reinterpret_cast<float4*>(gv + c) = t;
    }
}

// ---------------------------------------------------------------------------
// K2 (R8/R12 winning layout, bits unchanged): one thread per (bt,n,h).
// ---------------------------------------------------------------------------
__global__ void k2_w_deg(const float* __restrict__ f,
                         const int* __restrict__ nn,
                         float* __restrict__ out_u)
{
    __shared__ float sm[Hh * Cc];
    int diag = d_diag_flags[0];
    for (int i = threadIdx.x; i < Hh * Cc; i += blockDim.x)
        sm[i] = diag ? d_Mdiag[i] : 1.0f;
    __syncthreads();

    int idx = blockIdx.x * blockDim.x + threadIdx.x;
    if (idx >= BTNH) return;
    int h  = idx & (Hh - 1);
    int n  = (idx >> 2) & (Nn - 1);
    int bt = idx >> 14;

    const float* src = diag ? f : g_buf;
    const int*   nrow  = nn + n * (Kk + 1) + 1;
    float* ubase = out_u + (((size_t)bt * Nn + n) * Kk) * Hh + h;

    const float* fvi = src + (size_t)idx * Cc;
    float fi[Cc], mv[Cc];
#pragma unroll
    for (int c = 0; c < Cc; c += 4) {
        float4 t = *reinterpret_cast<const float4*>(fvi + c);
        fi[c] = t.x; fi[c+1] = t.y; fi[c+2] = t.z; fi[c+3] = t.w;
    }
#pragma unroll
    for (int c = 0; c < Cc; c++) mv[c] = sm[h * Cc + c];

    const float* fbase = src + (size_t)bt * Nn * Hh * Cc;
    float deg = 0.f;
#pragma unroll 4
    for (int k = 0; k < Kk; k++) {
        int j = nrow[k];
        float w = 0.f;
        if (j >= 0) {
            const float* fj = fbase + ((size_t)j * Hh + h) * Cc;
            float s = 0.f;
#pragma unroll
            for (int c = 0; c < Cc; c += 4) {
                float4 t = *reinterpret_cast<const float4*>(fj + c);
                float a0 = __fmul_rn(mv[c],   __fsub_rn(fi[c],   t.x));
                float a1 = __fmul_rn(mv[c+1], __fsub_rn(fi[c+1], t.y));
                float a2 = __fmul_rn(mv[c+2], __fsub_rn(fi[c+2], t.z));
                float a3 = __fmul_rn(mv[c+3], __fsub_rn(fi[c+3], t.w));
                s = __fadd_rn(s, __fmul_rn(a0, a0));
                s = __fadd_rn(s, __fmul_rn(a1, a1));
                s = __fadd_rn(s, __fmul_rn(a2, a2));
                s = __fadd_rn(s, __fmul_rn(a3, a3));
            }
            w = ftz(expf(-s));
        }
        deg = __fadd_rn(deg, w);
        ubase[(size_t)k * Hh] = w;
    }
    deg_buf[idx] = deg;
}

// ---------------------------------------------------------------------------
// K3: one thread per edge (bt,n,k), float4 over h.
// R14 change: sqrt+div -> rsqrtf+mul. The FTZ flush decision (P) and the
// P>0 guard are bit-identical to R12; only non-flushed magnitudes move ~1e-7.
// ---------------------------------------------------------------------------
__global__ void __launch_bounds__(256) k3_normalize(
        const int* __restrict__ nn,
        float* __restrict__ out_u)
{
    size_t idx = (size_t)blockIdx.x * blockDim.x + threadIdx.x;
    if (idx >= NEDGE) return;
    int k  = (int)(idx & 15);
    int n  = (int)((idx >> 4) & (Nn - 1));
    int bt = (int)(idx >> 16);

    const float4* degv = reinterpret_cast<const float4*>(deg_buf);
    float4 di = degv[(size_t)bt * Nn + n];

    int j  = nn[n * (Kk + 1) + 1 + k];
    int jj = j % Nn; if (jj < 0) jj += Nn;
    float4 dj = degv[(size_t)bt * Nn + jj];

    float4* uv = reinterpret_cast<float4*>(out_u) + ((size_t)bt * Nn + n) * Kk + k;
    float4 u = *uv;

    float P;
    P = ftz(__fmul_rn(di.x, dj.x));
    u.x = (P > 0.f) ? ftz(__fmul_rn(u.x, rsqrtf(P))) : 0.f;
    P = ftz(__fmul_rn(di.y, dj.y));
    u.y = (P > 0.f) ? ftz(__fmul_rn(u.y, rsqrtf(P))) : 0.f;
    P = ftz(__fmul_rn(di.z, dj.z));
    u.z = (P > 0.f) ? ftz(__fmul_rn(u.z, rsqrtf(P))) : 0.f;
    P = ftz(__fmul_rn(di.w, dj.w));
    u.w = (P > 0.f) ? ftz(__fmul_rn(u.w, rsqrtf(P))) : 0.f;

    *uv = u;
}

// ---------------------------------------------------------------------------
// K4: temporal path. R14 change: expf -> __expf (d_w is O(1)-valued; ~4e-7
// relative error, far inside 1e-3 and invisible in the combined norm).
// ---------------------------------------------------------------------------
__global__ void k4_temporal(const float* __restrict__ f,
                            const float* __restrict__ Q,
                            float* __restrict__ out_d)
{
    __shared__ float sQ[Vv * Hh * Cc * Cc];
    __shared__ float sQd[Vv * Hh * Cc];
    int diag = d_diag_flags[1];
    if (diag) {
        for (int i = threadIdx.x; i < Vv * Hh * Cc; i += blockDim.x) sQd[i] = d_Qdiag[i];
    } else {
        for (int i = threadIdx.x; i < Vv * Hh * Cc * Cc; i += blockDim.x) sQ[i] = Q[i];
    }
    __syncthreads();

    int idx = blockIdx.x * blockDim.x + threadIdx.x;
    if (idx >= BRNH) return;
    int h  = idx & (Hh - 1);
    int n  = (idx >> 2) & (Nn - 1);
    int br = idx >> 14;
    int r  = br % (Tt - 1);
    int b  = br / (Tt - 1);
    int tcur = r + 1;

    const float* fb = f + (size_t)b * Tt * Nn * Hh * Cc;
    const float* fc = fb + (((size_t)tcur * Nn + n) * Hh + h) * Cc;

    float xc[Cc];
#pragma unroll
    for (int c = 0; c < Cc; c += 4) {
        float4 t = *reinterpret_cast<const float4*>(fc + c);
        xc[c] = t.x; xc[c+1] = t.y; xc[c+2] = t.z; xc[c+3] = t.w;
    }

    float wd[Vv];
    float indeg = 0.f;
#pragma unroll
    for (int v = 0; v < Vv; v++) {
        float w = 0.f;
        if (v <= r) {
            int tp = r - v;
            const float* fp = fb + (((size_t)tp * Nn + n) * Hh + h) * Cc;
            float d[Cc];
#pragma unroll
            for (int c = 0; c < Cc; c += 4) {
                float4 t = *reinterpret_cast<const float4*>(fp + c);
                d[c]   = __fsub_rn(t.x, xc[c]);
                d[c+1] = __fsub_rn(t.y, xc[c+1]);
                d[c+2] = __fsub_rn(t.z, xc[c+2]);
                d[c+3] = __fsub_rn(t.w, xc[c+3]);
            }
            if (diag) {
                const float* qv = sQd + (v * Hh + h) * Cc;
#pragma unroll
                for (int i = 0; i < Cc; i++) {
                    float a = __fmul_rn(qv[i], d[i]);
                    float e = __expf(-__fmul_rn(a, a));
                    w = __fadd_rn(w, e);
                }
            } else {
                const float* Qh = sQ + (v * Hh + h) * Cc * Cc;
#pragma unroll
                for (int i = 0; i < Cc; i++) {
                    float a = 0.f;
#pragma unroll
                    for (int jx = 0; jx < Cc; jx++)
                        a = __fadd_rn(a, __fmul_rn(Qh[i * Cc + jx], d[jx]));
                    float e = __expf(-__fmul_rn(a, a));
                    w = __fadd_rn(w, e);
                }
            }
        }
        wd[v] = w;
        indeg = __fadd_rn(indeg, w);
    }
    float inv = (indeg > 0.f) ? __fdiv_rn(1.f, indeg) : 0.f;

    size_t obase = ((size_t)(b * (Tt - 1) + r)) * Vv * Nn * Hh + (size_t)n * Hh + h;
#pragma unroll
    for (int v = 0; v < Vv; v++)
        out_d[obase + (size_t)v * Nn * Hh] = __fmul_rn(wd[v], inv);
}

// ---------------------------------------------------------------------------
extern "C" void kernel_launch(void* const* d_in, const int* in_sizes, int n_in,
                              void* d_out, int out_size)
{
    const float* features = nullptr;
    const float* multiQ   = nullptr;
    const float* multiM   = nullptr;
    const int*   nearest  = nullptr;
    for (int i = 0; i < n_in; i++) {
        switch (in_sizes[i]) {
            case SZ_FEATURES: features = (const float*)d_in[i]; break;
            case SZ_MULTIQ:   multiQ   = (const float*)d_in[i]; break;
            case SZ_MULTIM:   multiM   = (const float*)d_in[i]; break;
            case SZ_NEAREST:  nearest  = (const int*)  d_in[i]; break;
            default: break;
        }
    }

    float* out_u = (float*)d_out;
    float* out_d = (float*)d_out + U_SIZE;

    const int thr = 256;
    k0_analyze<<<1, 1024>>>(multiM, multiQ);
    k1_compute_g<<<(BTNH + thr - 1) / thr, thr>>>(features, multiM);   // no-op when diag
    k2_w_deg<<<(BTNH + thr - 1) / thr, thr>>>(features, nearest, out_u);
    k3_normalize<<<(int)((NEDGE + thr - 1) / thr), thr>>>(nearest, out_u);
    k4_temporal<<<(BRNH + thr - 1) / thr, thr>>>(features, multiQ, out_d);
}